// round 2
// baseline (speedup 1.0000x reference)
#include <cuda_runtime.h>
#include <math.h>

// ---------------------------------------------------------------------------
// HeisenbergAttention: B=8, T=2048, D=1024 fp32
//   q,k,v = x @ W{q,k,v}^T
//   temp  = clip(hbar / (||q||+1e-8), 0.1, 5.0)     (per query row)
//   S     = (q @ k^T) * temp[row]
//   A     = softmax(S, axis=-1)
//   out   = A @ v
// Round-1: exact fp32 SIMT tiled GEMMs (tensor-core split-bf16 path reserved
// for later rounds once ncu baseline exists).
// ---------------------------------------------------------------------------

#define BM 128
#define BN 128
#define BK 16
#define TM 8
#define TN 8

static const int BATCH = 8;
static const int T = 2048;
static const int D = 1024;
static const int MTOT = BATCH * T;     // 16384

// Scratch (allocation-free rule: __device__ globals)
__device__ float g_q[16777216];        // 16384 x 1024
__device__ float g_k[16777216];
__device__ float g_v[16777216];
__device__ float g_s[33554432];        // 8 x 2048 x 2048
__device__ float g_temp[16384];

// ---------------------------------------------------------------------------
// GEMM C = A @ B^T.  A: M x K row-major (ld=K). B: N x K row-major (ld=K).
// C: M x ldc row-major. Optional per-row scale applied in epilogue.
// blockIdx.z batches with byte strides sA/sB/sC (element strides).
// Requires M%128==0, N%128==0, K%16==0, 256 threads.
// ---------------------------------------------------------------------------
__global__ __launch_bounds__(256)
void gemm_abt(const float* __restrict__ A, const float* __restrict__ B,
              float* __restrict__ C, int K, int ldc,
              long sA, long sB, long sC,
              const float* __restrict__ rowScale, int sScale)
{
    const float* Ab = A + (long)blockIdx.z * sA;
    const float* Bb = B + (long)blockIdx.z * sB;
    float*       Cb = C + (long)blockIdx.z * sC;

    __shared__ float As[BK][BM];
    __shared__ float Bs[BK][BN];

    const int tid = threadIdx.x;
    const int tx  = tid & 15;
    const int ty  = tid >> 4;
    const int m0  = blockIdx.y * BM;
    const int n0  = blockIdx.x * BN;

    float acc[TM][TN];
#pragma unroll
    for (int i = 0; i < TM; i++)
#pragma unroll
        for (int j = 0; j < TN; j++) acc[i][j] = 0.0f;

    for (int k0 = 0; k0 < K; k0 += BK) {
#pragma unroll
        for (int i = 0; i < 2; i++) {
            int idx = tid + i * 256;          // 0..511 float4 slots
            int row = idx >> 2;               // 0..127
            int c4  = (idx & 3) << 2;         // 0,4,8,12
            float4 v = *(const float4*)(Ab + (long)(m0 + row) * K + k0 + c4);
            As[c4 + 0][row] = v.x; As[c4 + 1][row] = v.y;
            As[c4 + 2][row] = v.z; As[c4 + 3][row] = v.w;
        }
#pragma unroll
        for (int i = 0; i < 2; i++) {
            int idx = tid + i * 256;
            int row = idx >> 2;
            int c4  = (idx & 3) << 2;
            float4 v = *(const float4*)(Bb + (long)(n0 + row) * K + k0 + c4);
            Bs[c4 + 0][row] = v.x; Bs[c4 + 1][row] = v.y;
            Bs[c4 + 2][row] = v.z; Bs[c4 + 3][row] = v.w;
        }
        __syncthreads();

#pragma unroll
        for (int k = 0; k < BK; k++) {
            float4 a0 = *(const float4*)&As[k][ty * TM];
            float4 a1 = *(const float4*)&As[k][ty * TM + 4];
            float4 b0 = *(const float4*)&Bs[k][tx * TN];
            float4 b1 = *(const float4*)&Bs[k][tx * TN + 4];
            float a[TM] = {a0.x, a0.y, a0.z, a0.w, a1.x, a1.y, a1.z, a1.w};
            float b[TN] = {b0.x, b0.y, b0.z, b0.w, b1.x, b1.y, b1.z, b1.w};
#pragma unroll
            for (int i = 0; i < TM; i++)
#pragma unroll
                for (int j = 0; j < TN; j++)
                    acc[i][j] = fmaf(a[i], b[j], acc[i][j]);
        }
        __syncthreads();
    }

#pragma unroll
    for (int i = 0; i < TM; i++) {
        int m = m0 + ty * TM + i;
        float sc = 1.0f;
        if (rowScale) sc = rowScale[(long)blockIdx.z * sScale + m];
        float* crow = Cb + (long)m * ldc + n0 + tx * TN;
        float4 o0 = make_float4(acc[i][0]*sc, acc[i][1]*sc, acc[i][2]*sc, acc[i][3]*sc);
        float4 o1 = make_float4(acc[i][4]*sc, acc[i][5]*sc, acc[i][6]*sc, acc[i][7]*sc);
        *(float4*)(crow + 0) = o0;
        *(float4*)(crow + 4) = o1;
    }
}

// ---------------------------------------------------------------------------
// GEMM C = A @ B.  A: M x K row-major (ld=K). B: K x N row-major (ld=N=ldc).
// ---------------------------------------------------------------------------
__global__ __launch_bounds__(256)
void gemm_ab(const float* __restrict__ A, const float* __restrict__ B,
             float* __restrict__ C, int K, int ldc,
             long sA, long sB, long sC)
{
    const float* Ab = A + (long)blockIdx.z * sA;
    const float* Bb = B + (long)blockIdx.z * sB;
    float*       Cb = C + (long)blockIdx.z * sC;

    __shared__ float As[BK][BM];
    __shared__ float Bs[BK][BN];

    const int tid = threadIdx.x;
    const int tx  = tid & 15;
    const int ty  = tid >> 4;
    const int m0  = blockIdx.y * BM;
    const int n0  = blockIdx.x * BN;

    float acc[TM][TN];
#pragma unroll
    for (int i = 0; i < TM; i++)
#pragma unroll
        for (int j = 0; j < TN; j++) acc[i][j] = 0.0f;

    for (int k0 = 0; k0 < K; k0 += BK) {
#pragma unroll
        for (int i = 0; i < 2; i++) {
            int idx = tid + i * 256;
            int row = idx >> 2;
            int c4  = (idx & 3) << 2;
            float4 v = *(const float4*)(Ab + (long)(m0 + row) * K + k0 + c4);
            As[c4 + 0][row] = v.x; As[c4 + 1][row] = v.y;
            As[c4 + 2][row] = v.z; As[c4 + 3][row] = v.w;
        }
#pragma unroll
        for (int i = 0; i < 2; i++) {
            int idx = tid + i * 256;          // B tile: 16 rows x 128 cols
            int row = idx >> 5;               // 0..15 (k within tile)
            int col = (idx & 31) << 2;        // 0..124
            float4 v = *(const float4*)(Bb + (long)(k0 + row) * ldc + n0 + col);
            *(float4*)&Bs[row][col] = v;
        }
        __syncthreads();

#pragma unroll
        for (int k = 0; k < BK; k++) {
            float4 a0 = *(const float4*)&As[k][ty * TM];
            float4 a1 = *(const float4*)&As[k][ty * TM + 4];
            float4 b0 = *(const float4*)&Bs[k][tx * TN];
            float4 b1 = *(const float4*)&Bs[k][tx * TN + 4];
            float a[TM] = {a0.x, a0.y, a0.z, a0.w, a1.x, a1.y, a1.z, a1.w};
            float b[TN] = {b0.x, b0.y, b0.z, b0.w, b1.x, b1.y, b1.z, b1.w};
#pragma unroll
            for (int i = 0; i < TM; i++)
#pragma unroll
                for (int j = 0; j < TN; j++)
                    acc[i][j] = fmaf(a[i], b[j], acc[i][j]);
        }
        __syncthreads();
    }

#pragma unroll
    for (int i = 0; i < TM; i++) {
        int m = m0 + ty * TM + i;
        float* crow = Cb + (long)m * ldc + n0 + tx * TN;
        *(float4*)(crow + 0) = make_float4(acc[i][0], acc[i][1], acc[i][2], acc[i][3]);
        *(float4*)(crow + 4) = make_float4(acc[i][4], acc[i][5], acc[i][6], acc[i][7]);
    }
}

// ---------------------------------------------------------------------------
// Block reductions (256 threads, 8 warps)
// ---------------------------------------------------------------------------
__device__ __forceinline__ float blockReduceSum(float v) {
    __shared__ float sh[33];
#pragma unroll
    for (int o = 16; o > 0; o >>= 1) v += __shfl_xor_sync(0xffffffffu, v, o);
    int lane = threadIdx.x & 31, w = threadIdx.x >> 5;
    __syncthreads();
    if (lane == 0) sh[w] = v;
    __syncthreads();
    if (w == 0) {
        v = (lane < 8) ? sh[lane] : 0.0f;
#pragma unroll
        for (int o = 4; o > 0; o >>= 1) v += __shfl_xor_sync(0xffffffffu, v, o);
        if (lane == 0) sh[32] = v;
    }
    __syncthreads();
    return sh[32];
}

__device__ __forceinline__ float blockReduceMax(float v) {
    __shared__ float sh[33];
#pragma unroll
    for (int o = 16; o > 0; o >>= 1) v = fmaxf(v, __shfl_xor_sync(0xffffffffu, v, o));
    int lane = threadIdx.x & 31, w = threadIdx.x >> 5;
    __syncthreads();
    if (lane == 0) sh[w] = v;
    __syncthreads();
    if (w == 0) {
        v = (lane < 8) ? sh[lane] : -INFINITY;
#pragma unroll
        for (int o = 4; o > 0; o >>= 1) v = fmaxf(v, __shfl_xor_sync(0xffffffffu, v, o));
        if (lane == 0) sh[32] = v;
    }
    __syncthreads();
    return sh[32];
}

// temp[row] = clip(hbar / (||q_row|| + 1e-8), 0.1, 5.0)
__global__ __launch_bounds__(256)
void temp_kernel(const float* __restrict__ q, const float* __restrict__ hbar,
                 float* __restrict__ temp)
{
    const float* r = q + (long)blockIdx.x * D;
    float s = 0.0f;
    for (int i = threadIdx.x; i < D; i += 256) { float v = r[i]; s = fmaf(v, v, s); }
    s = blockReduceSum(s);
    if (threadIdx.x == 0) {
        float t = hbar[0] / (sqrtf(s) + 1e-8f);
        temp[blockIdx.x] = fminf(fmaxf(t, 0.1f), 5.0f);
    }
}

// In-place row softmax, rows of length 2048, 256 threads (8 elems/thread)
__global__ __launch_bounds__(256)
void softmax_kernel(float* __restrict__ S)
{
    float* r = S + (long)blockIdx.x * 2048;
    const int tid = threadIdx.x;
    float v[8];
    float mx = -INFINITY;
#pragma unroll
    for (int i = 0; i < 8; i++) { v[i] = r[tid + i * 256]; mx = fmaxf(mx, v[i]); }
    mx = blockReduceMax(mx);
    float s = 0.0f;
#pragma unroll
    for (int i = 0; i < 8; i++) { v[i] = expf(v[i] - mx); s += v[i]; }
    s = blockReduceSum(s);
    float inv = 1.0f / s;
#pragma unroll
    for (int i = 0; i < 8; i++) r[tid + i * 256] = v[i] * inv;
}

// ---------------------------------------------------------------------------
extern "C" void kernel_launch(void* const* d_in, const int* in_sizes, int n_in,
                              void* d_out, int out_size)
{
    const float* x    = (const float*)d_in[0];
    const float* Wq   = (const float*)d_in[1];
    const float* Wk   = (const float*)d_in[2];
    const float* Wv   = (const float*)d_in[3];
    const float* hbar = (const float*)d_in[4];
    float* out = (float*)d_out;

    float *q, *k, *v, *s, *tp;
    cudaGetSymbolAddress((void**)&q,  g_q);
    cudaGetSymbolAddress((void**)&k,  g_k);
    cudaGetSymbolAddress((void**)&v,  g_v);
    cudaGetSymbolAddress((void**)&s,  g_s);
    cudaGetSymbolAddress((void**)&tp, g_temp);

    dim3 blk(256);

    // Projections: (16384 x 1024) @ (1024 x 1024)^T
    dim3 gp(D / BN, MTOT / BM, 1);                       // (8, 128, 1)
    gemm_abt<<<gp, blk>>>(x, Wq, q, D, D, 0, 0, 0, nullptr, 0);
    gemm_abt<<<gp, blk>>>(x, Wk, k, D, D, 0, 0, 0, nullptr, 0);
    gemm_abt<<<gp, blk>>>(x, Wv, v, D, D, 0, 0, 0, nullptr, 0);

    // Per-row adaptive temperature from ||q||
    temp_kernel<<<MTOT, blk>>>(q, hbar, tp);

    // Scores: per batch (2048 x 1024) @ (2048 x 1024)^T, scaled by temp[row]
    dim3 gs(T / BN, T / BM, BATCH);                      // (16, 16, 8)
    gemm_abt<<<gs, blk>>>(q, k, s, D, T,
                          (long)T * D, (long)T * D, (long)T * T, tp, T);

    // Row softmax over 16384 rows of length 2048
    softmax_kernel<<<MTOT, blk>>>(s);

    // Output: per batch (2048 x 2048) @ (2048 x 1024)
    dim3 go(D / BN, T / BM, BATCH);                      // (8, 16, 8)
    gemm_ab<<<go, blk>>>(s, v, out, T, D,
                         (long)T * T, (long)T * D, (long)T * D);
}

// round 3
// speedup vs baseline: 1.0004x; 1.0004x over previous
#include <cuda_runtime.h>
#include <math.h>

// ---------------------------------------------------------------------------
// HeisenbergAttention: B=8, T=2048, D=1024 fp32
//   q,k,v = x @ W{q,k,v}^T
//   temp  = clip(hbar / (||q||+1e-8), 0.1, 5.0)     (per query row)
//   S     = (q @ k^T) * temp[row]
//   A     = softmax(S, axis=-1)
//   out   = A @ v
// Round-1: exact fp32 SIMT tiled GEMMs (tensor-core split-bf16 path reserved
// for later rounds once ncu baseline exists).
// ---------------------------------------------------------------------------

#define BM 128
#define BN 128
#define BK 16
#define TM 8
#define TN 8

static const int BATCH = 8;
static const int T = 2048;
static const int D = 1024;
static const int MTOT = BATCH * T;     // 16384

// Scratch (allocation-free rule: __device__ globals)
__device__ float g_q[16777216];        // 16384 x 1024
__device__ float g_k[16777216];
__device__ float g_v[16777216];
__device__ float g_s[33554432];        // 8 x 2048 x 2048
__device__ float g_temp[16384];

// ---------------------------------------------------------------------------
// GEMM C = A @ B^T.  A: M x K row-major (ld=K). B: N x K row-major (ld=K).
// C: M x ldc row-major. Optional per-row scale applied in epilogue.
// blockIdx.z batches with byte strides sA/sB/sC (element strides).
// Requires M%128==0, N%128==0, K%16==0, 256 threads.
// ---------------------------------------------------------------------------
__global__ __launch_bounds__(256)
void gemm_abt(const float* __restrict__ A, const float* __restrict__ B,
              float* __restrict__ C, int K, int ldc,
              long sA, long sB, long sC,
              const float* __restrict__ rowScale, int sScale)
{
    const float* Ab = A + (long)blockIdx.z * sA;
    const float* Bb = B + (long)blockIdx.z * sB;
    float*       Cb = C + (long)blockIdx.z * sC;

    __shared__ float As[BK][BM];
    __shared__ float Bs[BK][BN];

    const int tid = threadIdx.x;
    const int tx  = tid & 15;
    const int ty  = tid >> 4;
    const int m0  = blockIdx.y * BM;
    const int n0  = blockIdx.x * BN;

    float acc[TM][TN];
#pragma unroll
    for (int i = 0; i < TM; i++)
#pragma unroll
        for (int j = 0; j < TN; j++) acc[i][j] = 0.0f;

    for (int k0 = 0; k0 < K; k0 += BK) {
#pragma unroll
        for (int i = 0; i < 2; i++) {
            int idx = tid + i * 256;          // 0..511 float4 slots
            int row = idx >> 2;               // 0..127
            int c4  = (idx & 3) << 2;         // 0,4,8,12
            float4 v = *(const float4*)(Ab + (long)(m0 + row) * K + k0 + c4);
            As[c4 + 0][row] = v.x; As[c4 + 1][row] = v.y;
            As[c4 + 2][row] = v.z; As[c4 + 3][row] = v.w;
        }
#pragma unroll
        for (int i = 0; i < 2; i++) {
            int idx = tid + i * 256;
            int row = idx >> 2;
            int c4  = (idx & 3) << 2;
            float4 v = *(const float4*)(Bb + (long)(n0 + row) * K + k0 + c4);
            Bs[c4 + 0][row] = v.x; Bs[c4 + 1][row] = v.y;
            Bs[c4 + 2][row] = v.z; Bs[c4 + 3][row] = v.w;
        }
        __syncthreads();

#pragma unroll
        for (int k = 0; k < BK; k++) {
            float4 a0 = *(const float4*)&As[k][ty * TM];
            float4 a1 = *(const float4*)&As[k][ty * TM + 4];
            float4 b0 = *(const float4*)&Bs[k][tx * TN];
            float4 b1 = *(const float4*)&Bs[k][tx * TN + 4];
            float a[TM] = {a0.x, a0.y, a0.z, a0.w, a1.x, a1.y, a1.z, a1.w};
            float b[TN] = {b0.x, b0.y, b0.z, b0.w, b1.x, b1.y, b1.z, b1.w};
#pragma unroll
            for (int i = 0; i < TM; i++)
#pragma unroll
                for (int j = 0; j < TN; j++)
                    acc[i][j] = fmaf(a[i], b[j], acc[i][j]);
        }
        __syncthreads();
    }

#pragma unroll
    for (int i = 0; i < TM; i++) {
        int m = m0 + ty * TM + i;
        float sc = 1.0f;
        if (rowScale) sc = rowScale[(long)blockIdx.z * sScale + m];
        float* crow = Cb + (long)m * ldc + n0 + tx * TN;
        float4 o0 = make_float4(acc[i][0]*sc, acc[i][1]*sc, acc[i][2]*sc, acc[i][3]*sc);
        float4 o1 = make_float4(acc[i][4]*sc, acc[i][5]*sc, acc[i][6]*sc, acc[i][7]*sc);
        *(float4*)(crow + 0) = o0;
        *(float4*)(crow + 4) = o1;
    }
}

// ---------------------------------------------------------------------------
// GEMM C = A @ B.  A: M x K row-major (ld=K). B: K x N row-major (ld=N=ldc).
// ---------------------------------------------------------------------------
__global__ __launch_bounds__(256)
void gemm_ab(const float* __restrict__ A, const float* __restrict__ B,
             float* __restrict__ C, int K, int ldc,
             long sA, long sB, long sC)
{
    const float* Ab = A + (long)blockIdx.z * sA;
    const float* Bb = B + (long)blockIdx.z * sB;
    float*       Cb = C + (long)blockIdx.z * sC;

    __shared__ float As[BK][BM];
    __shared__ float Bs[BK][BN];

    const int tid = threadIdx.x;
    const int tx  = tid & 15;
    const int ty  = tid >> 4;
    const int m0  = blockIdx.y * BM;
    const int n0  = blockIdx.x * BN;

    float acc[TM][TN];
#pragma unroll
    for (int i = 0; i < TM; i++)
#pragma unroll
        for (int j = 0; j < TN; j++) acc[i][j] = 0.0f;

    for (int k0 = 0; k0 < K; k0 += BK) {
#pragma unroll
        for (int i = 0; i < 2; i++) {
            int idx = tid + i * 256;
            int row = idx >> 2;
            int c4  = (idx & 3) << 2;
            float4 v = *(const float4*)(Ab + (long)(m0 + row) * K + k0 + c4);
            As[c4 + 0][row] = v.x; As[c4 + 1][row] = v.y;
            As[c4 + 2][row] = v.z; As[c4 + 3][row] = v.w;
        }
#pragma unroll
        for (int i = 0; i < 2; i++) {
            int idx = tid + i * 256;          // B tile: 16 rows x 128 cols
            int row = idx >> 5;               // 0..15 (k within tile)
            int col = (idx & 31) << 2;        // 0..124
            float4 v = *(const float4*)(Bb + (long)(k0 + row) * ldc + n0 + col);
            *(float4*)&Bs[row][col] = v;
        }
        __syncthreads();

#pragma unroll
        for (int k = 0; k < BK; k++) {
            float4 a0 = *(const float4*)&As[k][ty * TM];
            float4 a1 = *(const float4*)&As[k][ty * TM + 4];
            float4 b0 = *(const float4*)&Bs[k][tx * TN];
            float4 b1 = *(const float4*)&Bs[k][tx * TN + 4];
            float a[TM] = {a0.x, a0.y, a0.z, a0.w, a1.x, a1.y, a1.z, a1.w};
            float b[TN] = {b0.x, b0.y, b0.z, b0.w, b1.x, b1.y, b1.z, b1.w};
#pragma unroll
            for (int i = 0; i < TM; i++)
#pragma unroll
                for (int j = 0; j < TN; j++)
                    acc[i][j] = fmaf(a[i], b[j], acc[i][j]);
        }
        __syncthreads();
    }

#pragma unroll
    for (int i = 0; i < TM; i++) {
        int m = m0 + ty * TM + i;
        float* crow = Cb + (long)m * ldc + n0 + tx * TN;
        *(float4*)(crow + 0) = make_float4(acc[i][0], acc[i][1], acc[i][2], acc[i][3]);
        *(float4*)(crow + 4) = make_float4(acc[i][4], acc[i][5], acc[i][6], acc[i][7]);
    }
}

// ---------------------------------------------------------------------------
// Block reductions (256 threads, 8 warps)
// ---------------------------------------------------------------------------
__device__ __forceinline__ float blockReduceSum(float v) {
    __shared__ float sh[33];
#pragma unroll
    for (int o = 16; o > 0; o >>= 1) v += __shfl_xor_sync(0xffffffffu, v, o);
    int lane = threadIdx.x & 31, w = threadIdx.x >> 5;
    __syncthreads();
    if (lane == 0) sh[w] = v;
    __syncthreads();
    if (w == 0) {
        v = (lane < 8) ? sh[lane] : 0.0f;
#pragma unroll
        for (int o = 4; o > 0; o >>= 1) v += __shfl_xor_sync(0xffffffffu, v, o);
        if (lane == 0) sh[32] = v;
    }
    __syncthreads();
    return sh[32];
}

__device__ __forceinline__ float blockReduceMax(float v) {
    __shared__ float sh[33];
#pragma unroll
    for (int o = 16; o > 0; o >>= 1) v = fmaxf(v, __shfl_xor_sync(0xffffffffu, v, o));
    int lane = threadIdx.x & 31, w = threadIdx.x >> 5;
    __syncthreads();
    if (lane == 0) sh[w] = v;
    __syncthreads();
    if (w == 0) {
        v = (lane < 8) ? sh[lane] : -INFINITY;
#pragma unroll
        for (int o = 4; o > 0; o >>= 1) v = fmaxf(v, __shfl_xor_sync(0xffffffffu, v, o));
        if (lane == 0) sh[32] = v;
    }
    __syncthreads();
    return sh[32];
}

// temp[row] = clip(hbar / (||q_row|| + 1e-8), 0.1, 5.0)
__global__ __launch_bounds__(256)
void temp_kernel(const float* __restrict__ q, const float* __restrict__ hbar,
                 float* __restrict__ temp)
{
    const float* r = q + (long)blockIdx.x * D;
    float s = 0.0f;
    for (int i = threadIdx.x; i < D; i += 256) { float v = r[i]; s = fmaf(v, v, s); }
    s = blockReduceSum(s);
    if (threadIdx.x == 0) {
        float t = hbar[0] / (sqrtf(s) + 1e-8f);
        temp[blockIdx.x] = fminf(fmaxf(t, 0.1f), 5.0f);
    }
}

// In-place row softmax, rows of length 2048, 256 threads (8 elems/thread)
__global__ __launch_bounds__(256)
void softmax_kernel(float* __restrict__ S)
{
    float* r = S + (long)blockIdx.x * 2048;
    const int tid = threadIdx.x;
    float v[8];
    float mx = -INFINITY;
#pragma unroll
    for (int i = 0; i < 8; i++) { v[i] = r[tid + i * 256]; mx = fmaxf(mx, v[i]); }
    mx = blockReduceMax(mx);
    float s = 0.0f;
#pragma unroll
    for (int i = 0; i < 8; i++) { v[i] = expf(v[i] - mx); s += v[i]; }
    s = blockReduceSum(s);
    float inv = 1.0f / s;
#pragma unroll
    for (int i = 0; i < 8; i++) r[tid + i * 256] = v[i] * inv;
}

// ---------------------------------------------------------------------------
extern "C" void kernel_launch(void* const* d_in, const int* in_sizes, int n_in,
                              void* d_out, int out_size)
{
    const float* x    = (const float*)d_in[0];
    const float* Wq   = (const float*)d_in[1];
    const float* Wk   = (const float*)d_in[2];
    const float* Wv   = (const float*)d_in[3];
    const float* hbar = (const float*)d_in[4];
    float* out = (float*)d_out;

    float *q, *k, *v, *s, *tp;
    cudaGetSymbolAddress((void**)&q,  g_q);
    cudaGetSymbolAddress((void**)&k,  g_k);
    cudaGetSymbolAddress((void**)&v,  g_v);
    cudaGetSymbolAddress((void**)&s,  g_s);
    cudaGetSymbolAddress((void**)&tp, g_temp);

    dim3 blk(256);

    // Projections: (16384 x 1024) @ (1024 x 1024)^T
    dim3 gp(D / BN, MTOT / BM, 1);                       // (8, 128, 1)
    gemm_abt<<<gp, blk>>>(x, Wq, q, D, D, 0, 0, 0, nullptr, 0);
    gemm_abt<<<gp, blk>>>(x, Wk, k, D, D, 0, 0, 0, nullptr, 0);
    gemm_abt<<<gp, blk>>>(x, Wv, v, D, D, 0, 0, 0, nullptr, 0);

    // Per-row adaptive temperature from ||q||
    temp_kernel<<<MTOT, blk>>>(q, hbar, tp);

    // Scores: per batch (2048 x 1024) @ (2048 x 1024)^T, scaled by temp[row]
    dim3 gs(T / BN, T / BM, BATCH);                      // (16, 16, 8)
    gemm_abt<<<gs, blk>>>(q, k, s, D, T,
                          (long)T * D, (long)T * D, (long)T * T, tp, T);

    // Row softmax over 16384 rows of length 2048
    softmax_kernel<<<MTOT, blk>>>(s);

    // Output: per batch (2048 x 2048) @ (2048 x 1024)
    dim3 go(D / BN, T / BM, BATCH);                      // (8, 16, 8)
    gemm_ab<<<go, blk>>>(s, v, out, T, D,
                         (long)T * T, (long)T * D, (long)T * D);
}